// round 4
// baseline (speedup 1.0000x reference)
#include <cuda_runtime.h>
#include <math.h>

#define NCLS 97
#define SEGS 8               // segments per block
#define ROWS (SEGS * 8)      // 64 rows per block
#define NTHR 64              // one thread per row
#define MAXB 8192

// Per-block partials. Static scratch — no allocs.
__device__ float g_block[MAXB];

__global__ __launch_bounds__(NTHR)
void atloss_kernel(const float* __restrict__ logits,
                   const float* __restrict__ labels,
                   const int*   __restrict__ pos,
                   int E, int N)
{
    __shared__ __align__(16) float s_log[ROWS * NCLS];   // 64 x 97 = 24832 B
    __shared__ __align__(16) float s_lab[SEGS * NCLS];   // 8 x 97  = 3104 B
    __shared__ float s_warp[2];
    __shared__ int   s_st;

    const int tid  = threadIdx.x;
    const int lane = tid & 31;
    const int wid  = tid >> 5;
    const int e0   = blockIdx.x * SEGS;

    // Phase 1: segment start + labels into smem (coalesced float4).
    if (tid == 0) s_st = pos[2 * e0];
    {
        const float4* src = (const float4*)(labels + (size_t)e0 * NCLS); // 776 floats, 16B aligned
        float4* dst = (float4*)s_lab;
        #pragma unroll
        for (int i = tid; i < (SEGS * NCLS) / 4; i += NTHR) dst[i] = src[i];
    }
    __syncthreads();

    // Phase 2: logits into smem (pure stream, 1552 float4 per block) + zero label col0.
    {
        const float4* src = (const float4*)(logits + (size_t)s_st * NCLS);
        float4* dst = (float4*)s_log;
        #pragma unroll 5
        for (int i = tid; i < (ROWS * NCLS) / 4; i += NTHR) dst[i] = src[i];
    }
    if (tid < SEGS) s_lab[tid * NCLS] = 0.0f;   // reference: labels[:,0] = 0
    __syncthreads();

    // Phase 3: loss2 — each thread owns one row. Masked LSE minus logit[row,0].
    // Bank pattern: addr = tid*97 + c -> tid + c (mod 32): conflict-free.
    float part;
    {
        const float* row = s_log + tid * NCLS;
        const float* lb  = s_lab + (tid >> 3) * NCLS;
        float v0 = row[0];
        float s  = __expf(v0);                       // col 0 always kept
        #pragma unroll 16
        for (int c = 1; c < NCLS; c++) {
            float v = row[c];
            float l = lb[c];
            s += (l == 0.0f) ? __expf(v) : 0.0f;     // n_mask excludes labels==1
        }
        part = (__logf(s) - v0) / (float)N;          // loss2 / N
    }

    // Phase 4: loss1 — 8 threads per segment, column-strided over 97 cols.
    {
        const int   j      = tid & 7;                // lane within segment group
        const float* segrow = s_log + (tid & ~7) * NCLS;
        const float* lb     = s_lab + (tid >> 3) * NCLS;

        float S1 = 0.0f, npos = 0.0f, psum = 0.0f;
        for (int c = j; c < NCLS; c += 8) {
            float m = segrow[c];
            #pragma unroll
            for (int r = 1; r < 8; r++) m = fmaxf(m, segrow[r * NCLS + c]);
            float l = lb[c];
            bool  p = (l != 0.0f) || (c == 0);       // p_mask: positives + col0
            S1   += p ? __expf(m) : 0.0f;
            npos += l;
            psum += l * m;
        }
        #pragma unroll
        for (int o = 1; o < 8; o <<= 1) {            // reduce within 8-lane group
            S1   += __shfl_xor_sync(0xFFFFFFFFu, S1,   o);
            npos += __shfl_xor_sync(0xFFFFFFFFu, npos, o);
            psum += __shfl_xor_sync(0xFFFFFFFFu, psum, o);
        }
        if (j == 0)                                   // one contribution per segment
            part += (npos * __logf(S1) - psum) / (float)E;
    }

    // Phase 5: block reduction (warp shuffle + tiny smem fold).
    #pragma unroll
    for (int o = 16; o; o >>= 1) part += __shfl_xor_sync(0xFFFFFFFFu, part, o);
    if (lane == 0) s_warp[wid] = part;
    __syncthreads();
    if (tid == 0) g_block[blockIdx.x] = s_warp[0] + s_warp[1];
}

// Deterministic reduction of 8192 partials: shuffle-based, one barrier.
__global__ __launch_bounds__(1024)
void atloss_reduce_kernel(float* __restrict__ out, int nb)
{
    __shared__ double sdw[32];
    const int tid  = threadIdx.x;
    const int lane = tid & 31;
    const int wid  = tid >> 5;

    double acc = 0.0;
    for (int i = tid; i < nb; i += 1024) acc += (double)g_block[i];
    #pragma unroll
    for (int o = 16; o; o >>= 1) acc += __shfl_xor_sync(0xFFFFFFFFu, acc, o);
    if (lane == 0) sdw[wid] = acc;
    __syncthreads();
    if (wid == 0) {
        double a = sdw[lane];
        #pragma unroll
        for (int o = 16; o; o >>= 1) a += __shfl_xor_sync(0xFFFFFFFFu, a, o);
        if (lane == 0) out[0] = (float)a;
    }
}

extern "C" void kernel_launch(void* const* d_in, const int* in_sizes, int n_in,
                              void* d_out, int out_size)
{
    const float* logits = (const float*)d_in[0];
    const float* labels = (const float*)d_in[1];
    const int*   pos    = (const int*)d_in[2];
    float* out = (float*)d_out;

    const int N  = in_sizes[0] / NCLS;   // 524288
    const int E  = in_sizes[1] / NCLS;   // 65536
    const int nb = E / SEGS;             // 8192 blocks

    atloss_kernel<<<nb, NTHR>>>(logits, labels, pos, E, N);
    atloss_reduce_kernel<<<1, 1024>>>(out, nb);
}

// round 5
// speedup vs baseline: 1.8231x; 1.8231x over previous
#include <cuda_runtime.h>
#include <math.h>

#define NCLS 97

// Final-accumulation state. Zero-initialized at module load; the last block of
// every launch resets it, so graph replays always start from zero.
__device__ double   g_sum;
__device__ unsigned g_count;

__global__ __launch_bounds__(256, 4)
void atloss_kernel(const float* __restrict__ logits,
                   const float* __restrict__ labels,
                   const int*   __restrict__ pos,
                   int E, int N, int nb, float* __restrict__ out)
{
    __shared__ float s_part[8];
    const int lane = threadIdx.x & 31;
    const int wid  = threadIdx.x >> 5;
    const int e    = blockIdx.x * 8 + wid;

    float part = 0.0f;
    if (e < E) {
        const int st  = pos[2 * e];
        const int len = pos[2 * e + 1] - st;          // == 8 here
        const float* seg = logits + (size_t)st * NCLS;
        const float* lab = labels + (size_t)e  * NCLS;

        // ---- labels: lane column slots c0=lane, c1=lane+32, c2=lane+64 ----
        float lab0 = lab[lane]; if (lane == 0) lab0 = 0.0f;   // labels[:,0]=0
        float lab1 = lab[lane + 32];
        float lab2 = lab[lane + 64];
        float lab96 = lab[96];                                 // broadcast load
        const float nm0 = (lab0 == 0.0f) ? 1.0f : 0.0f;        // n_mask
        const float nm1 = (lab1 == 0.0f) ? 1.0f : 0.0f;
        const float nm2 = (lab2 == 0.0f) ? 1.0f : 0.0f;

        // ---- per-lane auxiliary row data (lanes 0..len-1 own one row each) ----
        const bool aux = (lane < len);
        float row0_r = aux ? seg[lane * NCLS]      : 0.0f;       // logits[row,0]
        float r96    = aux ? seg[lane * NCLS + 96] : -INFINITY;  // col 96 of row

        // ---- front-batched row loads: 24 independent LDGs ----
        float a[8], b[8], c[8];
        #pragma unroll
        for (int r = 0; r < 8; r++) {
            const float* row = seg + r * NCLS;
            bool ok = (r < len);
            a[r] = ok ? row[lane]      : -INFINITY;
            b[r] = ok ? row[lane + 32] : -INFINITY;
            c[r] = ok ? row[lane + 64] : -INFINITY;
        }

        // ---- column maxima over rows (segment_max, cols 0..95) ----
        float cm0 = a[0], cm1 = b[0], cm2 = c[0];
        #pragma unroll
        for (int r = 1; r < 8; r++) {
            cm0 = fmaxf(cm0, a[r]); cm1 = fmaxf(cm1, b[r]); cm2 = fmaxf(cm2, c[r]);
        }

        // ---- per-row masked exp sums over cols 0..95 (exp(-INF)=0 pads) ----
        float t0 = nm0*__expf(a[0]) + nm1*__expf(b[0]) + nm2*__expf(c[0]);
        float t1 = nm0*__expf(a[1]) + nm1*__expf(b[1]) + nm2*__expf(c[1]);
        float t2 = nm0*__expf(a[2]) + nm1*__expf(b[2]) + nm2*__expf(c[2]);
        float t3 = nm0*__expf(a[3]) + nm1*__expf(b[3]) + nm2*__expf(c[3]);
        float t4 = nm0*__expf(a[4]) + nm1*__expf(b[4]) + nm2*__expf(c[4]);
        float t5 = nm0*__expf(a[5]) + nm1*__expf(b[5]) + nm2*__expf(c[5]);
        float t6 = nm0*__expf(a[6]) + nm1*__expf(b[6]) + nm2*__expf(c[6]);
        float t7 = nm0*__expf(a[7]) + nm1*__expf(b[7]) + nm2*__expf(c[7]);

        // ---- 8 interleaved butterfly sums: totals broadcast to all lanes ----
        #pragma unroll
        for (int o = 16; o; o >>= 1) {
            t0 += __shfl_xor_sync(0xFFFFFFFFu, t0, o);
            t1 += __shfl_xor_sync(0xFFFFFFFFu, t1, o);
            t2 += __shfl_xor_sync(0xFFFFFFFFu, t2, o);
            t3 += __shfl_xor_sync(0xFFFFFFFFu, t3, o);
            t4 += __shfl_xor_sync(0xFFFFFFFFu, t4, o);
            t5 += __shfl_xor_sync(0xFFFFFFFFu, t5, o);
            t6 += __shfl_xor_sync(0xFFFFFFFFu, t6, o);
            t7 += __shfl_xor_sync(0xFFFFFFFFu, t7, o);
        }

        // ---- lane r finishes row r: add its col-96 term, one batched log ----
        float sel = t0;
        sel = (lane == 1) ? t1 : sel;
        sel = (lane == 2) ? t2 : sel;
        sel = (lane == 3) ? t3 : sel;
        sel = (lane == 4) ? t4 : sel;
        sel = (lane == 5) ? t5 : sel;
        sel = (lane == 6) ? t6 : sel;
        sel = (lane == 7) ? t7 : sel;
        float e96  = (lab96 == 0.0f) ? __expf(r96) : 0.0f;   // 0 for lanes >= len
        float logv = __logf(sel + e96);                      // 8 logs in 1 MUFU slot
        float l2   = aux ? (logv - row0_r) : 0.0f;           // loss2 of row 'lane'

        // ---- col-96 segment max (butterfly over r96; -INF padding) ----
        float m96 = r96;
        #pragma unroll
        for (int o = 4; o; o >>= 1) m96 = fmaxf(m96, __shfl_xor_sync(0xFFFFFFFFu, m96, o));
        // lanes 0..7 all hold the group max; lane 0 consumes it below.

        // ---- loss1 lane terms ----
        bool p0 = (lab0 != 0.0f) || (lane == 0);              // p_mask: col0 + positives
        float S1   = (p0 ? __expf(cm0) : 0.0f)
                   + ((lab1 != 0.0f) ? __expf(cm1) : 0.0f)
                   + ((lab2 != 0.0f) ? __expf(cm2) : 0.0f);
        float npos = lab0 + lab1 + lab2;
        float psum = lab0 * cm0 + lab1 * cm1 + lab2 * cm2;
        if (lane == 0 && lab96 != 0.0f) {
            S1   += __expf(m96);
            npos += lab96;
            psum += lab96 * m96;
        }

        // ---- single combined warp reduction of the 4 quantities ----
        #pragma unroll
        for (int o = 16; o; o >>= 1) {
            S1   += __shfl_xor_sync(0xFFFFFFFFu, S1,   o);
            npos += __shfl_xor_sync(0xFFFFFFFFu, npos, o);
            psum += __shfl_xor_sync(0xFFFFFFFFu, psum, o);
            l2   += __shfl_xor_sync(0xFFFFFFFFu, l2,   o);
        }
        if (lane == 0)
            part = (npos * __logf(S1) - psum) / (float)E + l2 / (float)N;
    }

    // ---- block fold + global atomic tail (no second kernel) ----
    if (lane == 0) s_part[wid] = part;
    __syncthreads();
    if (threadIdx.x == 0) {
        float bsum = 0.0f;
        #pragma unroll
        for (int w = 0; w < 8; w++) bsum += s_part[w];
        atomicAdd(&g_sum, (double)bsum);
        __threadfence();
        unsigned t = atomicAdd(&g_count, 1u);
        if (t == (unsigned)(nb - 1)) {
            double v = *((volatile double*)&g_sum);
            out[0] = (float)v;
            *((volatile double*)&g_sum) = 0.0;     // self-clean for next replay
            *((volatile unsigned*)&g_count) = 0u;
        }
    }
}

extern "C" void kernel_launch(void* const* d_in, const int* in_sizes, int n_in,
                              void* d_out, int out_size)
{
    const float* logits = (const float*)d_in[0];
    const float* labels = (const float*)d_in[1];
    const int*   pos    = (const int*)d_in[2];
    float* out = (float*)d_out;

    const int N  = in_sizes[0] / NCLS;   // 524288
    const int E  = in_sizes[1] / NCLS;   // 65536
    const int nb = (E + 7) / 8;          // 8192 blocks, warp-per-segment

    atloss_kernel<<<nb, 256>>>(logits, labels, pos, E, N, nb, out);
}

// round 6
// speedup vs baseline: 1.8813x; 1.0319x over previous
#include <cuda_runtime.h>
#include <math.h>

#define NCLS 97
#define LOG2E 1.4426950408889634f

// Final-accumulation state. Zero-initialized at module load; the last block of
// every launch resets it, so graph replays always start from zero.
__device__ double   g_sum;
__device__ unsigned g_count;

__device__ __forceinline__ float ex2a(float x) {
    float y;
    asm("ex2.approx.ftz.f32 %0, %1;" : "=f"(y) : "f"(x));
    return y;   // ex2a(-INF) == 0
}

__global__ __launch_bounds__(256, 5)
void atloss_kernel(const float* __restrict__ logits,
                   const float* __restrict__ labels,
                   const int*   __restrict__ pos,
                   int E, int N, int nb, float* __restrict__ out)
{
    __shared__ float s_part[8];
    const int lane = threadIdx.x & 31;
    const int wid  = threadIdx.x >> 5;
    const int e    = blockIdx.x * 8 + wid;

    float part = 0.0f;
    if (e < E) {
        const int st  = pos[2 * e];
        const int len = pos[2 * e + 1] - st;          // == 8 here
        const float* seg = logits + (size_t)st * NCLS;
        const float* lab = labels + (size_t)e  * NCLS;

        // ---- labels: lane column slots c0=lane, c1=lane+32, c2=lane+64 ----
        float lab0 = lab[lane]; if (lane == 0) lab0 = 0.0f;   // labels[:,0]=0
        float lab1 = lab[lane + 32];
        float lab2 = lab[lane + 64];
        float lab96 = lab[96];                                 // broadcast load
        // n_mask bias folded into exp argument: 0 keeps, -INF kills.
        const float nb0 = (lab0 == 0.0f) ? 0.0f : -INFINITY;
        const float nb1 = (lab1 == 0.0f) ? 0.0f : -INFINITY;
        const float nb2 = (lab2 == 0.0f) ? 0.0f : -INFINITY;
        const float nb3 = (lab96 == 0.0f) ? 0.0f : -INFINITY;

        // ---- per-lane auxiliary row data (lanes 0..len-1 own one row each) ----
        const bool aux = (lane < len);
        float row0_r = aux ? seg[lane * NCLS]      : 0.0f;       // logits[row,0]
        float r96    = aux ? seg[lane * NCLS + 96] : -INFINITY;  // col 96 of row

        // ---- row loads: unconditional fast path (len == 8 always here) ----
        float a[8], b[8], c[8];
        if (len == 8) {
            #pragma unroll
            for (int r = 0; r < 8; r++) {
                const float* row = seg + r * NCLS;
                a[r] = row[lane];
                b[r] = row[lane + 32];
                c[r] = row[lane + 64];
            }
        } else {
            #pragma unroll
            for (int r = 0; r < 8; r++) {
                const float* row = seg + r * NCLS;
                bool ok = (r < len);
                a[r] = ok ? row[lane]      : -INFINITY;
                b[r] = ok ? row[lane + 32] : -INFINITY;
                c[r] = ok ? row[lane + 64] : -INFINITY;
            }
        }

        // ---- column maxima (segment_max) + per-row masked exp sums ----
        float cm0 = a[0], cm1 = b[0], cm2 = c[0];
        float t[8];
        t[0] = ex2a(fmaf(a[0], LOG2E, nb0)) + ex2a(fmaf(b[0], LOG2E, nb1))
             + ex2a(fmaf(c[0], LOG2E, nb2));
        #pragma unroll
        for (int r = 1; r < 8; r++) {
            cm0 = fmaxf(cm0, a[r]); cm1 = fmaxf(cm1, b[r]); cm2 = fmaxf(cm2, c[r]);
            t[r] = ex2a(fmaf(a[r], LOG2E, nb0)) + ex2a(fmaf(b[r], LOG2E, nb1))
                 + ex2a(fmaf(c[r], LOG2E, nb2));
        }

        // ---- 8 interleaved butterfly sums (totals broadcast to all lanes) ----
        #pragma unroll
        for (int o = 16; o; o >>= 1) {
            #pragma unroll
            for (int r = 0; r < 8; r++)
                t[r] += __shfl_xor_sync(0xFFFFFFFFu, t[r], o);
        }

        // ---- lane r finishes row r: add its col-96 term, one batched log ----
        float sel = t[0];
        #pragma unroll
        for (int r = 1; r < 8; r++) sel = (lane == r) ? t[r] : sel;
        float e96  = ex2a(fmaf(r96, LOG2E, nb3));            // 0 for lanes >= len
        float logv = __logf(sel + e96);                      // 8 logs, 1 MUFU slot
        float l2   = aux ? (logv - row0_r) : 0.0f;           // loss2 of row 'lane'

        // ---- col-96 segment max (butterfly over lanes 0..7; -INF padding) ----
        float m96 = r96;
        #pragma unroll
        for (int o = 4; o; o >>= 1) m96 = fmaxf(m96, __shfl_xor_sync(0xFFFFFFFFu, m96, o));

        // ---- loss1 lane terms (p_mask bias folded into exp args) ----
        bool p0 = (lab0 != 0.0f) || (lane == 0);
        const float pb0 = p0 ? 0.0f : -INFINITY;
        const float pb1 = (lab1 != 0.0f) ? 0.0f : -INFINITY;
        const float pb2 = (lab2 != 0.0f) ? 0.0f : -INFINITY;
        float S1   = ex2a(fmaf(cm0, LOG2E, pb0))
                   + ex2a(fmaf(cm1, LOG2E, pb1))
                   + ex2a(fmaf(cm2, LOG2E, pb2));
        float npos = lab0 + lab1 + lab2;
        float psum = lab0 * cm0 + lab1 * cm1 + lab2 * cm2;
        if (lane == 0 && lab96 != 0.0f) {
            S1   += ex2a(m96 * LOG2E);
            npos += lab96;
            psum += lab96 * m96;
        }

        // ---- single combined warp reduction of the 4 quantities ----
        #pragma unroll
        for (int o = 16; o; o >>= 1) {
            S1   += __shfl_xor_sync(0xFFFFFFFFu, S1,   o);
            npos += __shfl_xor_sync(0xFFFFFFFFu, npos, o);
            psum += __shfl_xor_sync(0xFFFFFFFFu, psum, o);
            l2   += __shfl_xor_sync(0xFFFFFFFFu, l2,   o);
        }
        if (lane == 0)
            part = (npos * __logf(S1) - psum) / (float)E + l2 / (float)N;
    }

    // ---- block fold + global atomic tail (no second kernel) ----
    if (lane == 0) s_part[wid] = part;
    __syncthreads();
    if (threadIdx.x == 0) {
        float bsum = 0.0f;
        #pragma unroll
        for (int w = 0; w < 8; w++) bsum += s_part[w];
        atomicAdd(&g_sum, (double)bsum);
        __threadfence();
        unsigned tkt = atomicAdd(&g_count, 1u);
        if (tkt == (unsigned)(nb - 1)) {
            double v = *((volatile double*)&g_sum);
            out[0] = (float)v;
            *((volatile double*)&g_sum) = 0.0;     // self-clean for next replay
            *((volatile unsigned*)&g_count) = 0u;
        }
    }
}

extern "C" void kernel_launch(void* const* d_in, const int* in_sizes, int n_in,
                              void* d_out, int out_size)
{
    const float* logits = (const float*)d_in[0];
    const float* labels = (const float*)d_in[1];
    const int*   pos    = (const int*)d_in[2];
    float* out = (float*)d_out;

    const int N  = in_sizes[0] / NCLS;   // 524288
    const int E  = in_sizes[1] / NCLS;   // 65536
    const int nb = (E + 7) / 8;          // 8192 blocks, warp-per-segment

    atloss_kernel<<<nb, 256>>>(logits, labels, pos, E, N, nb, out);
}